// round 13
// baseline (speedup 1.0000x reference)
#include <cuda_runtime.h>
#include <cuda_bf16.h>
#include <stdint.h>
#include <math.h>

#define B_  2
#define S_  2048
#define D_  1024
#define H_  16
#define HD_ 64
#define ROWS_ (B_*S_)   // 4096

// ---------------- scratch (device globals; no allocations) ----------------
__device__ float g_xn  [ROWS_*D_];    // k-permuted within 8-blocks
__device__ float g_qkv [ROWS_*3*D_];
__device__ float g_attn[ROWS_*D_];    // k-permuted within 8-blocks
__device__ float g_wqt [D_*3*D_];     // tf32-rounded w_qkv
__device__ float g_wot [D_*D_];       // tf32-rounded w_out
__device__ float2 g_rtab[S_*32];      // RoPE cos/sin table
__device__ __nv_bfloat16 g_qh[B_*H_*S_*HD_];
__device__ __nv_bfloat16 g_ql[B_*H_*S_*HD_];
__device__ __nv_bfloat16 g_kh[B_*H_*S_*HD_];
__device__ __nv_bfloat16 g_kl[B_*H_*S_*HD_];
__device__ __nv_bfloat16 g_vh[B_*H_*S_*HD_];
__device__ __nv_bfloat16 g_vl[B_*H_*S_*HD_];

// ---------------- helpers ----------------
__device__ __forceinline__ uint32_t f2tf32(float x) {
    uint32_t r;
    asm("cvt.rna.tf32.f32 %0, %1;" : "=r"(r) : "f"(x));
    return r;
}
__device__ __forceinline__ float rnd_tf32(float x) {
    return __uint_as_float(f2tf32(x));
}

#define MMA_TF32(d, a, b)                                              \
    asm volatile("mma.sync.aligned.m16n8k8.row.col.f32.tf32.tf32.f32 " \
        "{%0,%1,%2,%3}, {%4,%5,%6,%7}, {%8,%9}, {%0,%1,%2,%3};"        \
        : "+f"((d)[0]), "+f"((d)[1]), "+f"((d)[2]), "+f"((d)[3])       \
        : "r"((a)[0]), "r"((a)[1]), "r"((a)[2]), "r"((a)[3]),          \
          "r"((b)[0]), "r"((b)[1]))

#define CP16(dst, src)                                                     \
    asm volatile("cp.async.ca.shared.global [%0], [%1], 16;"               \
        :: "r"(dst), "l"(src))
#define CP_COMMIT()  asm volatile("cp.async.commit_group;")
#define CP_WAIT(n)   asm volatile("cp.async.wait_group %0;" :: "n"(n))

// ---------------- kernel 0a: tf32-round a float array ----------------
__global__ __launch_bounds__(256) void cvt_tf32_kernel(
    const float* __restrict__ in, float* __restrict__ out)
{
    const int i = blockIdx.x * 256 + threadIdx.x;
    float4 v = ((const float4*)in)[i];
    v.x = rnd_tf32(v.x); v.y = rnd_tf32(v.y);
    v.z = rnd_tf32(v.z); v.w = rnd_tf32(v.w);
    ((float4*)out)[i] = v;
}

// ---------------- kernel 0b: RoPE table (fp64 once per (s,freq)) ----------
__global__ __launch_bounds__(256) void rope_tab_kernel(float2* __restrict__ tab)
{
    const int i = blockIdx.x * 256 + threadIdx.x;   // 0..65535
    const int s = i >> 5, f = i & 31;
    double invf = exp(-0.28782313662425575 * (double)f); // ln(10000)/32
    double sn, cs;
    sincos((double)s * invf, &sn, &cs);
    tab[i] = make_float2((float)cs, (float)sn);
}

// ---------------- kernel 1: LayerNorm -> tf32, k-pair-permuted ----------------
// value at col k is stored at position (k & ~7) + perm(k&7), perm: pairs (t,t+4)
// land adjacently: order 0,4,1,5,2,6,3,7.
__global__ __launch_bounds__(256) void ln_kernel(
    const float* __restrict__ x, const float* __restrict__ g,
    const float* __restrict__ b, float* __restrict__ y)
{
    __shared__ float red[16];
    const int row = blockIdx.x, tid = threadIdx.x;
    const float* xr = x + (size_t)row * D_;
    float4 v = *(const float4*)(xr + (tid << 2));
    float s  = v.x + v.y + v.z + v.w;
    float ss = v.x*v.x + v.y*v.y + v.z*v.z + v.w*v.w;
#pragma unroll
    for (int off = 16; off; off >>= 1) {
        s  += __shfl_xor_sync(0xffffffffu, s,  off);
        ss += __shfl_xor_sync(0xffffffffu, ss, off);
    }
    if ((tid & 31) == 0) { red[tid >> 5] = s; red[8 + (tid >> 5)] = ss; }
    __syncthreads();
    if (tid < 8) {
        float a = red[tid], c = red[8 + tid];
#pragma unroll
        for (int off = 4; off; off >>= 1) {
            a += __shfl_xor_sync(0xffu, a, off);
            c += __shfl_xor_sync(0xffu, c, off);
        }
        if (tid == 0) { red[0] = a; red[8] = c; }
    }
    __syncthreads();
    const float mean = red[0] * (1.f / 1024.f);
    const float var  = red[8] * (1.f / 1024.f) - mean * mean;
    const float r    = rsqrtf(var + 1e-6f);
    const int c = tid << 2;
    float4 gv = *(const float4*)(g + c);
    float4 bv = *(const float4*)(b + c);
    float o0 = rnd_tf32((v.x - mean) * r * gv.x + bv.x);
    float o1 = rnd_tf32((v.y - mean) * r * gv.y + bv.y);
    float o2 = rnd_tf32((v.z - mean) * r * gv.z + bv.z);
    float o3 = rnd_tf32((v.w - mean) * r * gv.w + bv.w);
    // permuted store: cols c..c+3 -> (c&~7)+start + {0,2,4,6}, start = (c&4)?1:0
    float* yb = y + (size_t)row * D_ + (c & ~7) + ((c & 4) ? 1 : 0);
    yb[0] = o0; yb[2] = o1; yb[4] = o2; yb[6] = o3;
}

// ---------------- kernel 2/5: tf32 GEMM + bias, cp.async 4-stage ----------
// A must be tf32-rounded AND k-pair-permuted (pairs (t,t+4) adjacent).
// Bm must be tf32-rounded, standard layout. C = A @ Bm + bias.
__global__ __launch_bounds__(256) void tf32_gemm_bias(
    const float* __restrict__ A, const float* __restrict__ Bm,
    const float* __restrict__ bias, float* __restrict__ C,
    int M, int N, int K)
{
    constexpr int AP = 24, BP = 136;
    constexpr int ASZ = 128 * AP;   // uints per A stage
    constexpr int BSZ = 16 * BP;    // uints per B stage
    extern __shared__ uint32_t gsm[];
    uint32_t* As = gsm;             // 4 stages
    uint32_t* Bs = gsm + 4 * ASZ;

    const int tid  = threadIdx.x;
    const int wid  = tid >> 5, lane = tid & 31;
    const int g    = lane >> 2, t = lane & 3;
    const int wm   = wid & 1;
    const int wn   = wid >> 1;
    const int m0   = blockIdx.y << 7, n0 = blockIdx.x << 7;

    const uint32_t smemB = (uint32_t)__cvta_generic_to_shared(gsm);

    float acc[4][4][4];
#pragma unroll
    for (int mi = 0; mi < 4; mi++)
#pragma unroll
        for (int ni = 0; ni < 4; ni++)
#pragma unroll
            for (int r = 0; r < 4; r++) acc[mi][ni][r] = 0.f;

    auto load_stage = [&](int st, int ks) {
        const float* Asrc = A  + (size_t)m0 * K + ks * 16;
        const float* Bsrc = Bm + (size_t)(ks * 16) * N + n0;
        const uint32_t aB = smemB + (st * ASZ) * 4;
        const uint32_t bB = smemB + (4 * ASZ + st * BSZ) * 4;
#pragma unroll
        for (int it = 0; it < 2; ++it) {
            const int c  = tid + (it << 8);
            const int ar = c >> 2,  ak = (c & 3) << 2;
            CP16(aB + (ar * AP + ak) * 4, Asrc + (size_t)ar * K + ak);
            const int br = c >> 5,  bc = (c & 31) << 2;
            CP16(bB + (br * BP + bc) * 4, Bsrc + (size_t)br * N + bc);
        }
    };

    load_stage(0, 0); CP_COMMIT();
    load_stage(1, 1); CP_COMMIT();
    load_stage(2, 2); CP_COMMIT();

    const int KSTEPS = K >> 4;
    for (int ks = 0; ks < KSTEPS; ++ks) {
        CP_WAIT(2);
        __syncthreads();
        if (ks + 3 < KSTEPS) load_stage((ks + 3) & 3, ks + 3);
        CP_COMMIT();

        const int buf = ks & 3;
        const uint32_t* Ab = As + buf * ASZ;
        const uint32_t* Bb = Bs + buf * BSZ;

#pragma unroll
        for (int kk = 0; kk < 16; kk += 8) {
            uint32_t af[4][4], bfr[4][2];
#pragma unroll
            for (int mi = 0; mi < 4; mi++) {
                const int rb = wm * 64 + mi * 16;
                // paired layout: one 64-bit load gives (k=t, k=t+4)
                uint2 p0 = *(const uint2*)&Ab[(rb + g)     * AP + kk + 2 * t];
                uint2 p1 = *(const uint2*)&Ab[(rb + 8 + g) * AP + kk + 2 * t];
                af[mi][0] = p0.x; af[mi][1] = p1.x;
                af[mi][2] = p0.y; af[mi][3] = p1.y;
            }
#pragma unroll
            for (int ni = 0; ni < 4; ni++) {
                const int cb = wn * 32 + ni * 8 + g;
                bfr[ni][0] = Bb[(kk + t)     * BP + cb];
                bfr[ni][1] = Bb[(kk + t + 4) * BP + cb];
            }
#pragma unroll
            for (int mi = 0; mi < 4; mi++)
#pragma unroll
                for (int ni = 0; ni < 4; ni++)
                    MMA_TF32(acc[mi][ni], af[mi], bfr[ni]);
        }
    }

#pragma unroll
    for (int mi = 0; mi < 4; mi++) {
        const int row0 = m0 + wm * 64 + mi * 16 + g;
#pragma unroll
        for (int ni = 0; ni < 4; ni++) {
            const int col = n0 + wn * 32 + ni * 8 + 2 * t;
            float2 bb = *(const float2*)(bias + col);
            float2 v0 = { acc[mi][ni][0] + bb.x, acc[mi][ni][1] + bb.y };
            float2 v1 = { acc[mi][ni][2] + bb.x, acc[mi][ni][3] + bb.y };
            *(float2*)(C + (size_t)row0 * N + col)       = v0;
            *(float2*)(C + (size_t)(row0 + 8) * N + col) = v1;
        }
    }
}

// ---------------- kernel 3: per-head LN + RoPE -> bf16 hi/lo ----------------
__device__ __forceinline__ float warp_allreduce_sum(float v) {
#pragma unroll
    for (int off = 16; off; off >>= 1) v += __shfl_xor_sync(0xffffffffu, v, off);
    return v;
}

__device__ __forceinline__ void split_store(
    __nv_bfloat16* hi, __nv_bfloat16* lo, size_t idx, float x)
{
    __nv_bfloat16 h = __float2bfloat16_rn(x);
    hi[idx] = h;
    lo[idx] = __float2bfloat16_rn(x - __bfloat162float(h));
}

__global__ __launch_bounds__(512) void qk_rope_kernel(
    const float* __restrict__ qkv, const float2* __restrict__ tab,
    const float* __restrict__ qsc, const float* __restrict__ ksc,
    __nv_bfloat16* __restrict__ Qh, __nv_bfloat16* __restrict__ Ql,
    __nv_bfloat16* __restrict__ Kh, __nv_bfloat16* __restrict__ Kl,
    __nv_bfloat16* __restrict__ Vh, __nv_bfloat16* __restrict__ Vl)
{
    const int bs   = blockIdx.x;
    const int b    = bs >> 11;
    const int s    = bs & (S_ - 1);
    const int h    = threadIdx.x >> 5;
    const int lane = threadIdx.x & 31;
    const float* base = qkv + (size_t)bs * (3 * D_) + h * HD_;

    float q0 = base[lane],        q1 = base[lane + 32];
    float k0 = base[1024 + lane], k1 = base[1024 + lane + 32];
    float v0 = base[2048 + lane], v1 = base[2048 + lane + 32];

    float mu  = warp_allreduce_sum(q0 + q1) * (1.f / 64.f);
    float d0  = q0 - mu, d1 = q1 - mu;
    float var = warp_allreduce_sum(d0*d0 + d1*d1) * (1.f / 64.f);
    float r   = rsqrtf(var + 1e-6f);
    float qn0 = d0 * r * qsc[lane];
    float qn1 = d1 * r * qsc[lane + 32];

    mu  = warp_allreduce_sum(k0 + k1) * (1.f / 64.f);
    d0  = k0 - mu; d1 = k1 - mu;
    var = warp_allreduce_sum(d0*d0 + d1*d1) * (1.f / 64.f);
    r   = rsqrtf(var + 1e-6f);
    float kn0 = d0 * r * ksc[lane];
    float kn1 = d1 * r * ksc[lane + 32];

    const float2 cs = tab[(s << 5) + lane];
    const float c = cs.x, si = cs.y;

    float qr0 = qn0 * c - qn1 * si;
    float qr1 = qn1 * c + qn0 * si;
    float kr0 = kn0 * c - kn1 * si;
    float kr1 = kn1 * c + kn0 * si;

    const size_t o = (((size_t)(b * H_ + h)) * S_ + s) * HD_ + lane;
    split_store(Qh, Ql, o,      qr0);
    split_store(Qh, Ql, o + 32, qr1);
    split_store(Kh, Kl, o,      kr0);
    split_store(Kh, Kl, o + 32, kr1);
    split_store(Vh, Vl, o,      v0);
    split_store(Vh, Vl, o + 32, v1);
}

// ---------------- bf16 mma helpers for attention ----------------
#define LDSM_X4(r0,r1,r2,r3,addr)                                          \
    asm volatile("ldmatrix.sync.aligned.m8n8.x4.shared.b16 {%0,%1,%2,%3}, [%4];" \
        : "=r"(r0), "=r"(r1), "=r"(r2), "=r"(r3) : "r"(addr))

#define LDSM_X4T(r0,r1,r2,r3,addr)                                         \
    asm volatile("ldmatrix.sync.aligned.m8n8.x4.trans.shared.b16 {%0,%1,%2,%3}, [%4];" \
        : "=r"(r0), "=r"(r1), "=r"(r2), "=r"(r3) : "r"(addr))

#define MMA_BF16(d, a0,a1,a2,a3, b0,b1)                                    \
    asm volatile("mma.sync.aligned.m16n8k16.row.col.f32.bf16.bf16.f32 "    \
        "{%0,%1,%2,%3}, {%4,%5,%6,%7}, {%8,%9}, {%0,%1,%2,%3};"            \
        : "+f"((d)[0]), "+f"((d)[1]), "+f"((d)[2]), "+f"((d)[3])           \
        : "r"(a0), "r"(a1), "r"(a2), "r"(a3), "r"(b0), "r"(b1))

__device__ __forceinline__ float ex2f(float x) {
    float y; asm("ex2.approx.f32 %0, %1;" : "=f"(y) : "f"(x)); return y;
}

#define TP 72
#define TSZ (64 * TP)          // halfs per 64x64 tile

__device__ __forceinline__ void cp_tile(
    uint32_t dst, const __nv_bfloat16* __restrict__ src, int tid)
{
#pragma unroll
    for (int it = 0; it < 4; ++it) {
        int c = tid + (it << 7);       // 0..511 chunks of 16B
        int r = c >> 3, cc = c & 7;
        CP16(dst + r * (TP * 2) + cc * 16, src + r * HD_ + cc * 8);
    }
}

// ---------------- kernel 4: flash attention (bf16x3, 128-row Q tile) -------
// Epilogue writes k-pair-permuted layout (feeds the out-proj GEMM's A side).
__global__ __launch_bounds__(128, 2) void attn_kernel(
    const __nv_bfloat16* __restrict__ Qh, const __nv_bfloat16* __restrict__ Ql,
    const __nv_bfloat16* __restrict__ Kh, const __nv_bfloat16* __restrict__ Kl,
    const __nv_bfloat16* __restrict__ Vh, const __nv_bfloat16* __restrict__ Vl,
    float* __restrict__ O)
{
    extern __shared__ __nv_bfloat16 sh[];   // [2 stages][4 tiles][TSZ]

    const int tid  = threadIdx.x;
    const int lane = tid & 31, w = tid >> 5;
    const int g    = lane >> 2, t = lane & 3;
    const int bh   = blockIdx.y;
    const int q0   = blockIdx.x << 7;       // 128-row Q tile

    const __nv_bfloat16* Kbh = Kh + (size_t)bh * S_ * HD_;
    const __nv_bfloat16* Kbl = Kl + (size_t)bh * S_ * HD_;
    const __nv_bfloat16* Vbh = Vh + (size_t)bh * S_ * HD_;
    const __nv_bfloat16* Vbl = Vl + (size_t)bh * S_ * HD_;

    const uint32_t shB = (uint32_t)__cvta_generic_to_shared(sh);

    // ---- Q A-fragments straight from gmem (once); two 16-row halves ----
    uint32_t qhf[2][4][4], qlf[2][4][4];
#pragma unroll
    for (int hf = 0; hf < 2; ++hf) {
        const __nv_bfloat16* Qbase = Qh + ((size_t)bh * S_ + q0 + (w << 5) + hf * 16) * HD_;
        const __nv_bfloat16* Qbl   = Ql + ((size_t)bh * S_ + q0 + (w << 5) + hf * 16) * HD_;
#pragma unroll
        for (int kb = 0; kb < 4; ++kb) {
            const int c0 = kb * 16 + 2 * t;
            qhf[hf][kb][0] = *(const uint32_t*)(Qbase + (size_t)g       * HD_ + c0);
            qhf[hf][kb][1] = *(const uint32_t*)(Qbase + (size_t)(g + 8) * HD_ + c0);
            qhf[hf][kb][2] = *(const uint32_t*)(Qbase + (size_t)g       * HD_ + c0 + 8);
            qhf[hf][kb][3] = *(const uint32_t*)(Qbase + (size_t)(g + 8) * HD_ + c0 + 8);
            qlf[hf][kb][0] = *(const uint32_t*)(Qbl   + (size_t)g       * HD_ + c0);
            qlf[hf][kb][1] = *(const uint32_t*)(Qbl   + (size_t)(g + 8) * HD_ + c0);
            qlf[hf][kb][2] = *(const uint32_t*)(Qbl   + (size_t)g       * HD_ + c0 + 8);
            qlf[hf][kb][3] = *(const uint32_t*)(Qbl   + (size_t)(g + 8) * HD_ + c0 + 8);
        }
    }

    const uint32_t kx4 = ((((lane >> 4) << 3) + (lane & 7)) * TP
                          + ((lane >> 3) & 1) * 8) * 2;
    const uint32_t vx4 = (((((lane >> 3) & 1) << 3) + (lane & 7)) * TP
                          + ((lane >> 4) & 1) * 8) * 2;

    float lsum[2][2] = {{0.f, 0.f}, {0.f, 0.f}};
    float o_[2][8][4];
#pragma unroll
    for (int hf = 0; hf < 2; hf++)
#pragma unroll
        for (int nb = 0; nb < 8; nb++)
#pragma unroll
            for (int j = 0; j < 4; j++) o_[hf][nb][j] = 0.f;

    const float SCALE = 0.18033688011112042f;  // log2(e)/8

    {
        const uint32_t st0 = shB;
        cp_tile(st0,                Kbh, tid);
        cp_tile(st0 + TSZ * 2,      Kbl, tid);
        cp_tile(st0 + 2 * TSZ * 2,  Vbh, tid);
        cp_tile(st0 + 3 * TSZ * 2,  Vbl, tid);
        CP_COMMIT();
    }

    int buf = 0;
    for (int kt = 0; kt < S_; kt += 64) {
        if (kt + 64 < S_) {
            const uint32_t stn = shB + (buf ^ 1) * 4 * TSZ * 2;
            const size_t goff = (size_t)(kt + 64) * HD_;
            cp_tile(stn,               Kbh + goff, tid);
            cp_tile(stn + TSZ * 2,     Kbl + goff, tid);
            cp_tile(stn + 2 * TSZ * 2, Vbh + goff, tid);
            cp_tile(stn + 3 * TSZ * 2, Vbl + goff, tid);
            CP_COMMIT();
            CP_WAIT(1);
        } else {
            CP_WAIT(0);
        }
        __syncthreads();

        const uint32_t KhiB = shB + buf * 4 * TSZ * 2;
        const uint32_t KloB = KhiB + TSZ * 2;
        const uint32_t VhiB = KhiB + 2 * TSZ * 2;
        const uint32_t VloB = KhiB + 3 * TSZ * 2;

        // ---- S = Q K^T for both 16-row halves; K ldmatrix shared ----
        float S[2][8][4];
#pragma unroll
        for (int hf = 0; hf < 2; hf++)
#pragma unroll
            for (int nb = 0; nb < 8; nb++)
#pragma unroll
                for (int j = 0; j < 4; j++) S[hf][nb][j] = 0.f;

#pragma unroll
        for (int nb = 0; nb < 8; nb += 2) {
#pragma unroll
            for (int kb = 0; kb < 4; ++kb) {
                const uint32_t off = kx4 + (nb * 8 * TP + kb * 16) * 2;
                uint32_t h0, h1, h2, h3, e0, e1, e2, e3;
                LDSM_X4(h0, h1, h2, h3, KhiB + off);
                LDSM_X4(e0, e1, e2, e3, KloB + off);
#pragma unroll
                for (int hf = 0; hf < 2; ++hf) {
                    MMA_BF16(S[hf][nb],   qhf[hf][kb][0], qhf[hf][kb][1], qhf[hf][kb][2], qhf[hf][kb][3], h0, h1);
                    MMA_BF16(S[hf][nb],   qhf[hf][kb][0], qhf[hf][kb][1], qhf[hf][kb][2], qhf[hf][kb][3], e0, e1);
                    MMA_BF16(S[hf][nb],   qlf[hf][kb][0], qlf[hf][kb][1], qlf[hf][kb][2], qlf[hf][kb][3], h0, h1);
                    MMA_BF16(S[hf][nb+1], qhf[hf][kb][0], qhf[hf][kb][1], qhf[hf][kb][2], qhf[hf][kb][3], h2, h3);
                    MMA_BF16(S[hf][nb+1], qhf[hf][kb][0], qhf[hf][kb][1], qhf[hf][kb][2], qhf[hf][kb][3], e2, e3);
                    MMA_BF16(S[hf][nb+1], qlf[hf][kb][0], qlf[hf][kb][1], qlf[hf][kb][2], qlf[hf][kb][3], h2, h3);
                }
            }
        }

        // ---- exact softmax numerator: P = 2^(S*log2e/8); accumulate l ----
#pragma unroll
        for (int hf = 0; hf < 2; ++hf)
#pragma unroll
            for (int nb = 0; nb < 8; ++nb) {
                S[hf][nb][0] = ex2f(S[hf][nb][0] * SCALE);
                S[hf][nb][1] = ex2f(S[hf][nb][1] * SCALE);
                S[hf][nb][2] = ex2f(S[hf][nb][2] * SCALE);
                S[hf][nb][3] = ex2f(S[hf][nb][3] * SCALE);
                lsum[hf][0] += S[hf][nb][0] + S[hf][nb][1];
                lsum[hf][1] += S[hf][nb][2] + S[hf][nb][3];
            }

        // ---- O += P V, both halves; V ldmatrix shared ----
#pragma unroll
        for (int kb = 0; kb < 4; ++kb) {
            uint32_t phi[2][4], plo[2][4];
#pragma unroll
            for (int hf = 0; hf < 2; ++hf)
#pragma unroll
                for (int half = 0; half < 2; ++half) {
                    const float c0 = S[hf][2 * kb + half][0], c1 = S[hf][2 * kb + half][1];
                    const float c2 = S[hf][2 * kb + half][2], c3 = S[hf][2 * kb + half][3];
                    __nv_bfloat162 h0 = __floats2bfloat162_rn(c0, c1);
                    __nv_bfloat162 h1 = __floats2bfloat162_rn(c2, c3);
                    __nv_bfloat162 e0 = __floats2bfloat162_rn(c0 - __bfloat162float(h0.x),
                                                              c1 - __bfloat162float(h0.y));
                    __nv_bfloat162 e1 = __floats2bfloat162_rn(c2 - __bfloat162float(h1.x),
                                                              c3 - __bfloat162float(h1.y));
                    phi[hf][2 * half]     = *(uint32_t*)&h0;
                    phi[hf][2 * half + 1] = *(uint32_t*)&h1;
                    plo[hf][2 * half]     = *(uint32_t*)&e0;
                    plo[hf][2 * half + 1] = *(uint32_t*)&e1;
                }
#pragma unroll
            for (int nb = 0; nb < 8; nb += 2) {
                const uint32_t off = vx4 + (kb * 16 * TP + nb * 8) * 2;
                uint32_t vh0, vh1, vh2, vh3, vl0, vl1, vl2, vl3;
                LDSM_X4T(vh0, vh1, vh2, vh3, VhiB + off);
                LDSM_X4T(vl0, vl1, vl2, vl3, VloB + off);
#pragma unroll
                for (int hf = 0; hf < 2; ++hf) {
                    MMA_BF16(o_[hf][nb],   phi[hf][0], phi[hf][1], phi[hf][2], phi[hf][3], vh0, vh1);
                    MMA_BF16(o_[hf][nb],   phi[hf][0], phi[hf][1], phi[hf][2], phi[hf][3], vl0, vl1);
                    MMA_BF16(o_[hf][nb],   plo[hf][0], plo[hf][1], plo[hf][2], plo[hf][3], vh0, vh1);
                    MMA_BF16(o_[hf][nb+1], phi[hf][0], phi[hf][1], phi[hf][2], phi[hf][3], vh2, vh3);
                    MMA_BF16(o_[hf][nb+1], phi[hf][0], phi[hf][1], phi[hf][2], phi[hf][3], vl2, vl3);
                    MMA_BF16(o_[hf][nb+1], plo[hf][0], plo[hf][1], plo[hf][2], plo[hf][3], vh2, vh3);
                }
            }
        }
        __syncthreads();
        buf ^= 1;
    }

    // ---- epilogue: reduce l, O /= l, tf32-round, k-pair-permuted store ----
    const int b = bh >> 4, h = bh & 15;
    // pair positions: value at (nb*8 + 2t) -> p0, (nb*8+2t+1) -> p0+2
    const int p0 = ((t & 1) << 2) + (t >> 1);
#pragma unroll
    for (int hf = 0; hf < 2; ++hf) {
        float l0 = lsum[hf][0], l1 = lsum[hf][1];
        l0 += __shfl_xor_sync(0xffffffffu, l0, 1);
        l0 += __shfl_xor_sync(0xffffffffu, l0, 2);
        l1 += __shfl_xor_sync(0xffffffffu, l1, 1);
        l1 += __shfl_xor_sync(0xffffffffu, l1, 2);
        const float inv0 = 1.f / l0, inv1 = 1.f / l1;
        const int row0 = q0 + (w << 5) + hf * 16 + g;
#pragma unroll
        for (int nb = 0; nb < 8; ++nb) {
            const int colb = h * HD_ + nb * 8;
            float* Or0 = O + (size_t)(b * S_ + row0) * D_ + colb;
            float* Or1 = O + (size_t)(b * S_ + row0 + 8) * D_ + colb;
            Or0[p0]     = rnd_tf32(o_[hf][nb][0] * inv0);
            Or0[p0 + 2] = rnd_tf32(o_[hf][nb][1] * inv0);
            Or1[p0]     = rnd_tf32(o_[hf][nb][2] * inv1);
            Or1[p0 + 2] = rnd_tf32(o_[hf][nb][3] * inv1);
        }
    }
}

// ---------------- launch ----------------
extern "C" void kernel_launch(void* const* d_in, const int* in_sizes, int n_in,
                              void* d_out, int out_size)
{
    const float* x        = (const float*)d_in[0];
    const float* w_qkv    = (const float*)d_in[1];
    const float* b_qkv    = (const float*)d_in[2];
    const float* w_out    = (const float*)d_in[3];
    const float* b_out    = (const float*)d_in[4];
    const float* ln_scale = (const float*)d_in[5];
    const float* ln_bias  = (const float*)d_in[6];
    const float* q_scale  = (const float*)d_in[7];
    const float* k_scale  = (const float*)d_in[8];
    float* out = (float*)d_out;

    float *xn, *qkv, *attn, *wqt, *wot;
    float2* rtab;
    __nv_bfloat16 *qh, *ql, *kh, *kl, *vh, *vl;
    cudaGetSymbolAddress((void**)&xn,   g_xn);
    cudaGetSymbolAddress((void**)&qkv,  g_qkv);
    cudaGetSymbolAddress((void**)&attn, g_attn);
    cudaGetSymbolAddress((void**)&wqt,  g_wqt);
    cudaGetSymbolAddress((void**)&wot,  g_wot);
    cudaGetSymbolAddress((void**)&rtab, g_rtab);
    cudaGetSymbolAddress((void**)&qh,   g_qh);
    cudaGetSymbolAddress((void**)&ql,   g_ql);
    cudaGetSymbolAddress((void**)&kh,   g_kh);
    cudaGetSymbolAddress((void**)&kl,   g_kl);
    cudaGetSymbolAddress((void**)&vh,   g_vh);
    cudaGetSymbolAddress((void**)&vl,   g_vl);

    const int attn_smem = 2 * 4 * TSZ * sizeof(__nv_bfloat16);          // 73728 B
    const int gemm_smem = 4 * (128 * 24 + 16 * 136) * sizeof(uint32_t); // 83968 B
    cudaFuncSetAttribute(attn_kernel, cudaFuncAttributeMaxDynamicSharedMemorySize, attn_smem);
    cudaFuncSetAttribute(tf32_gemm_bias, cudaFuncAttributeMaxDynamicSharedMemorySize, gemm_smem);

    // Order chosen so tf32_gemm_bias (QKV) is the 4th launch -> ncu profiles it.
    cvt_tf32_kernel<<<(D_ * 3 * D_) / 1024, 256>>>(w_qkv, wqt);
    ln_kernel<<<ROWS_, 256>>>(x, ln_scale, ln_bias, xn);
    rope_tab_kernel<<<(S_ * 32) / 256, 256>>>(rtab);
    tf32_gemm_bias<<<dim3((3 * D_) / 128, ROWS_ / 128), 256, gemm_smem>>>(
        xn, wqt, b_qkv, qkv, ROWS_, 3 * D_, D_);
    cvt_tf32_kernel<<<(D_ * D_) / 1024, 256>>>(w_out, wot);
    qk_rope_kernel<<<ROWS_, 512>>>(qkv, rtab, q_scale, k_scale, qh, ql, kh, kl, vh, vl);
    attn_kernel<<<dim3(S_ / 128, B_ * H_), 128, attn_smem>>>(qh, ql, kh, kl, vh, vl, attn);
    tf32_gemm_bias<<<dim3(D_ / 128, ROWS_ / 128), 256, gemm_smem>>>(
        attn, wot, b_out, out, ROWS_, D_, D_);
}

// round 15
// speedup vs baseline: 1.0248x; 1.0248x over previous
#include <cuda_runtime.h>
#include <cuda_bf16.h>
#include <stdint.h>
#include <math.h>

#define B_  2
#define S_  2048
#define D_  1024
#define H_  16
#define HD_ 64
#define ROWS_ (B_*S_)   // 4096

// ---------------- scratch (device globals; no allocations) ----------------
__device__ float g_xn  [ROWS_*D_];    // k-permuted within 8-blocks
__device__ float g_qkv [ROWS_*3*D_];
__device__ float g_attn[ROWS_*D_];    // k-permuted within 8-blocks
__device__ float g_wqt [D_*3*D_];     // tf32-rounded w_qkv
__device__ float g_wot [D_*D_];       // tf32-rounded w_out
__device__ float2 g_rtab[S_*32];      // RoPE cos/sin table
__device__ __nv_bfloat16 g_qh[B_*H_*S_*HD_];
__device__ __nv_bfloat16 g_ql[B_*H_*S_*HD_];
__device__ __nv_bfloat16 g_kh[B_*H_*S_*HD_];
__device__ __nv_bfloat16 g_kl[B_*H_*S_*HD_];
__device__ __nv_bfloat16 g_vh[B_*H_*S_*HD_];
__device__ __nv_bfloat16 g_vl[B_*H_*S_*HD_];

// ---------------- helpers ----------------
__device__ __forceinline__ uint32_t f2tf32(float x) {
    uint32_t r;
    asm("cvt.rna.tf32.f32 %0, %1;" : "=r"(r) : "f"(x));
    return r;
}
__device__ __forceinline__ float rnd_tf32(float x) {
    return __uint_as_float(f2tf32(x));
}

#define MMA_TF32(d, a, b)                                              \
    asm volatile("mma.sync.aligned.m16n8k8.row.col.f32.tf32.tf32.f32 " \
        "{%0,%1,%2,%3}, {%4,%5,%6,%7}, {%8,%9}, {%0,%1,%2,%3};"        \
        : "+f"((d)[0]), "+f"((d)[1]), "+f"((d)[2]), "+f"((d)[3])       \
        : "r"((a)[0]), "r"((a)[1]), "r"((a)[2]), "r"((a)[3]),          \
          "r"((b)[0]), "r"((b)[1]))

#define CP16(dst, src)                                                     \
    asm volatile("cp.async.ca.shared.global [%0], [%1], 16;"               \
        :: "r"(dst), "l"(src))
#define CP16CG(dst, src)                                                   \
    asm volatile("cp.async.cg.shared.global [%0], [%1], 16;"               \
        :: "r"(dst), "l"(src))
#define CP_COMMIT()  asm volatile("cp.async.commit_group;")
#define CP_WAIT(n)   asm volatile("cp.async.wait_group %0;" :: "n"(n))

// ---------------- kernel 0a: tf32-round a float array ----------------
__global__ __launch_bounds__(256) void cvt_tf32_kernel(
    const float* __restrict__ in, float* __restrict__ out)
{
    const int i = blockIdx.x * 256 + threadIdx.x;
    float4 v = ((const float4*)in)[i];
    v.x = rnd_tf32(v.x); v.y = rnd_tf32(v.y);
    v.z = rnd_tf32(v.z); v.w = rnd_tf32(v.w);
    ((float4*)out)[i] = v;
}

// ---------------- kernel 0b: RoPE table (fp64 once per (s,freq)) ----------
__global__ __launch_bounds__(256) void rope_tab_kernel(float2* __restrict__ tab)
{
    const int i = blockIdx.x * 256 + threadIdx.x;   // 0..65535
    const int s = i >> 5, f = i & 31;
    double invf = exp(-0.28782313662425575 * (double)f); // ln(10000)/32
    double sn, cs;
    sincos((double)s * invf, &sn, &cs);
    tab[i] = make_float2((float)cs, (float)sn);
}

// ---------------- kernel 1: LayerNorm -> tf32, k-pair-permuted ----------------
__global__ __launch_bounds__(256) void ln_kernel(
    const float* __restrict__ x, const float* __restrict__ g,
    const float* __restrict__ b, float* __restrict__ y)
{
    __shared__ float red[16];
    const int row = blockIdx.x, tid = threadIdx.x;
    const float* xr = x + (size_t)row * D_;
    float4 v = *(const float4*)(xr + (tid << 2));
    float s  = v.x + v.y + v.z + v.w;
    float ss = v.x*v.x + v.y*v.y + v.z*v.z + v.w*v.w;
#pragma unroll
    for (int off = 16; off; off >>= 1) {
        s  += __shfl_xor_sync(0xffffffffu, s,  off);
        ss += __shfl_xor_sync(0xffffffffu, ss, off);
    }
    if ((tid & 31) == 0) { red[tid >> 5] = s; red[8 + (tid >> 5)] = ss; }
    __syncthreads();
    if (tid < 8) {
        float a = red[tid], c = red[8 + tid];
#pragma unroll
        for (int off = 4; off; off >>= 1) {
            a += __shfl_xor_sync(0xffu, a, off);
            c += __shfl_xor_sync(0xffu, c, off);
        }
        if (tid == 0) { red[0] = a; red[8] = c; }
    }
    __syncthreads();
    const float mean = red[0] * (1.f / 1024.f);
    const float var  = red[8] * (1.f / 1024.f) - mean * mean;
    const float r    = rsqrtf(var + 1e-6f);
    const int c = tid << 2;
    float4 gv = *(const float4*)(g + c);
    float4 bv = *(const float4*)(b + c);
    float o0 = rnd_tf32((v.x - mean) * r * gv.x + bv.x);
    float o1 = rnd_tf32((v.y - mean) * r * gv.y + bv.y);
    float o2 = rnd_tf32((v.z - mean) * r * gv.z + bv.z);
    float o3 = rnd_tf32((v.w - mean) * r * gv.w + bv.w);
    float* yb = y + (size_t)row * D_ + (c & ~7) + ((c & 4) ? 1 : 0);
    yb[0] = o0; yb[2] = o1; yb[4] = o2; yb[6] = o3;
}

// ---------------- kernel 2/5: tf32 GEMM + bias, k-step 32, 2-stage --------
// A tf32-rounded + k-pair-permuted; Bm tf32-rounded. C = A @ Bm + bias.
__global__ __launch_bounds__(256) void tf32_gemm_bias(
    const float* __restrict__ A, const float* __restrict__ Bm,
    const float* __restrict__ bias, float* __restrict__ C,
    int M, int N, int K)
{
    constexpr int AP = 40, BP = 132;   // uints; AP%32==8, BP%32==4 (conflict-free)
    constexpr int ASZ = 128 * AP;      // per stage
    constexpr int BSZ = 32 * BP;
    extern __shared__ uint32_t gsm[];
    uint32_t* As = gsm;                // 2 stages
    uint32_t* Bs = gsm + 2 * ASZ;

    const int tid  = threadIdx.x;
    const int wid  = tid >> 5, lane = tid & 31;
    const int g    = lane >> 2, t = lane & 3;
    const int wm   = wid & 1;
    const int wn   = wid >> 1;
    const int m0   = blockIdx.y << 7, n0 = blockIdx.x << 7;

    const uint32_t smemB = (uint32_t)__cvta_generic_to_shared(gsm);

    float acc[4][4][4];
#pragma unroll
    for (int mi = 0; mi < 4; mi++)
#pragma unroll
        for (int ni = 0; ni < 4; ni++)
#pragma unroll
            for (int r = 0; r < 4; r++) acc[mi][ni][r] = 0.f;

    auto load_stage = [&](int st, int ks) {
        const float* Asrc = A  + (size_t)m0 * K + ks * 32;
        const float* Bsrc = Bm + (size_t)(ks * 32) * N + n0;
        const uint32_t aB = smemB + (st * ASZ) * 4;
        const uint32_t bB = smemB + (2 * ASZ + st * BSZ) * 4;
#pragma unroll
        for (int it = 0; it < 4; ++it) {
            const int c  = tid + (it << 8);          // 0..1023
            const int ar = c >> 3,  ak = (c & 7) << 2;
            CP16CG(aB + (ar * AP + ak) * 4, Asrc + (size_t)ar * K + ak);
            const int br = c >> 5,  bc = (c & 31) << 2;
            CP16CG(bB + (br * BP + bc) * 4, Bsrc + (size_t)br * N + bc);
        }
    };

    load_stage(0, 0); CP_COMMIT();

    const int KS = K >> 5;   // 32
    int buf = 0;
    for (int ks = 0; ks < KS; ++ks) {
        if (ks + 1 < KS) {
            load_stage(buf ^ 1, ks + 1);
            CP_COMMIT();
            CP_WAIT(1);
        } else {
            CP_WAIT(0);
        }
        __syncthreads();

        const uint32_t* Ab = As + buf * ASZ;
        const uint32_t* Bb = Bs + buf * BSZ;

#pragma unroll
        for (int kk = 0; kk < 32; kk += 8) {
            uint32_t af[4][4], bfr[4][2];
#pragma unroll
            for (int mi = 0; mi < 4; mi++) {
                const int rb = wm * 64 + mi * 16;
                uint2 p0 = *(const uint2*)&Ab[(rb + g)     * AP + kk + 2 * t];
                uint2 p1 = *(const uint2*)&Ab[(rb + 8 + g) * AP + kk + 2 * t];
                af[mi][0] = p0.x; af[mi][1] = p1.x;
                af[mi][2] = p0.y; af[mi][3] = p1.y;
            }
#pragma unroll
            for (int ni = 0; ni < 4; ni++) {
                const int cb = wn * 32 + ni * 8 + g;
                bfr[ni][0] = Bb[(kk + t)     * BP + cb];
                bfr[ni][1] = Bb[(kk + t + 4) * BP + cb];
            }
#pragma unroll
            for (int mi = 0; mi < 4; mi++)
#pragma unroll
                for (int ni = 0; ni < 4; ni++)
                    MMA_TF32(acc[mi][ni], af[mi], bfr[ni]);
        }
        __syncthreads();
        buf ^= 1;
    }

#pragma unroll
    for (int mi = 0; mi < 4; mi++) {
        const int row0 = m0 + wm * 64 + mi * 16 + g;
#pragma unroll
        for (int ni = 0; ni < 4; ni++) {
            const int col = n0 + wn * 32 + ni * 8 + 2 * t;
            float2 bb = *(const float2*)(bias + col);
            float2 v0 = { acc[mi][ni][0] + bb.x, acc[mi][ni][1] + bb.y };
            float2 v1 = { acc[mi][ni][2] + bb.x, acc[mi][ni][3] + bb.y };
            *(float2*)(C + (size_t)row0 * N + col)       = v0;
            *(float2*)(C + (size_t)(row0 + 8) * N + col) = v1;
        }
    }
}

// ---------------- kernel 3: per-head LN + RoPE -> bf16 hi/lo ----------------
__device__ __forceinline__ float warp_allreduce_sum(float v) {
#pragma unroll
    for (int off = 16; off; off >>= 1) v += __shfl_xor_sync(0xffffffffu, v, off);
    return v;
}

__device__ __forceinline__ void split_store(
    __nv_bfloat16* hi, __nv_bfloat16* lo, size_t idx, float x)
{
    __nv_bfloat16 h = __float2bfloat16_rn(x);
    hi[idx] = h;
    lo[idx] = __float2bfloat16_rn(x - __bfloat162float(h));
}

__global__ __launch_bounds__(512) void qk_rope_kernel(
    const float* __restrict__ qkv, const float2* __restrict__ tab,
    const float* __restrict__ qsc, const float* __restrict__ ksc,
    __nv_bfloat16* __restrict__ Qh, __nv_bfloat16* __restrict__ Ql,
    __nv_bfloat16* __restrict__ Kh, __nv_bfloat16* __restrict__ Kl,
    __nv_bfloat16* __restrict__ Vh, __nv_bfloat16* __restrict__ Vl)
{
    const int bs   = blockIdx.x;
    const int b    = bs >> 11;
    const int s    = bs & (S_ - 1);
    const int h    = threadIdx.x >> 5;
    const int lane = threadIdx.x & 31;
    const float* base = qkv + (size_t)bs * (3 * D_) + h * HD_;

    float q0 = base[lane],        q1 = base[lane + 32];
    float k0 = base[1024 + lane], k1 = base[1024 + lane + 32];
    float v0 = base[2048 + lane], v1 = base[2048 + lane + 32];

    float mu  = warp_allreduce_sum(q0 + q1) * (1.f / 64.f);
    float d0  = q0 - mu, d1 = q1 - mu;
    float var = warp_allreduce_sum(d0*d0 + d1*d1) * (1.f / 64.f);
    float r   = rsqrtf(var + 1e-6f);
    float qn0 = d0 * r * qsc[lane];
    float qn1 = d1 * r * qsc[lane + 32];

    mu  = warp_allreduce_sum(k0 + k1) * (1.f / 64.f);
    d0  = k0 - mu; d1 = k1 - mu;
    var = warp_allreduce_sum(d0*d0 + d1*d1) * (1.f / 64.f);
    r   = rsqrtf(var + 1e-6f);
    float kn0 = d0 * r * ksc[lane];
    float kn1 = d1 * r * ksc[lane + 32];

    const float2 cs = tab[(s << 5) + lane];
    const float c = cs.x, si = cs.y;

    float qr0 = qn0 * c - qn1 * si;
    float qr1 = qn1 * c + qn0 * si;
    float kr0 = kn0 * c - kn1 * si;
    float kr1 = kn1 * c + kn0 * si;

    const size_t o = (((size_t)(b * H_ + h)) * S_ + s) * HD_ + lane;
    split_store(Qh, Ql, o,      qr0);
    split_store(Qh, Ql, o + 32, qr1);
    split_store(Kh, Kl, o,      kr0);
    split_store(Kh, Kl, o + 32, kr1);
    split_store(Vh, Vl, o,      v0);
    split_store(Vh, Vl, o + 32, v1);
}

// ---------------- bf16 mma helpers for attention ----------------
#define LDSM_X4(r0,r1,r2,r3,addr)                                          \
    asm volatile("ldmatrix.sync.aligned.m8n8.x4.shared.b16 {%0,%1,%2,%3}, [%4];" \
        : "=r"(r0), "=r"(r1), "=r"(r2), "=r"(r3) : "r"(addr))

#define LDSM_X4T(r0,r1,r2,r3,addr)                                         \
    asm volatile("ldmatrix.sync.aligned.m8n8.x4.trans.shared.b16 {%0,%1,%2,%3}, [%4];" \
        : "=r"(r0), "=r"(r1), "=r"(r2), "=r"(r3) : "r"(addr))

#define MMA_BF16(d, a0,a1,a2,a3, b0,b1)                                    \
    asm volatile("mma.sync.aligned.m16n8k16.row.col.f32.bf16.bf16.f32 "    \
        "{%0,%1,%2,%3}, {%4,%5,%6,%7}, {%8,%9}, {%0,%1,%2,%3};"            \
        : "+f"((d)[0]), "+f"((d)[1]), "+f"((d)[2]), "+f"((d)[3])           \
        : "r"(a0), "r"(a1), "r"(a2), "r"(a3), "r"(b0), "r"(b1))

__device__ __forceinline__ float ex2f(float x) {
    float y; asm("ex2.approx.f32 %0, %1;" : "=f"(y) : "f"(x)); return y;
}

#define TP 72
#define TSZ (64 * TP)

__device__ __forceinline__ void cp_tile(
    uint32_t dst, const __nv_bfloat16* __restrict__ src, int tid)
{
#pragma unroll
    for (int it = 0; it < 4; ++it) {
        int c = tid + (it << 7);
        int r = c >> 3, cc = c & 7;
        CP16(dst + r * (TP * 2) + cc * 16, src + r * HD_ + cc * 8);
    }
}

// ---------------- kernel 4: flash attention (bf16x3, 128-row Q tile) -------
__global__ __launch_bounds__(128, 2) void attn_kernel(
    const __nv_bfloat16* __restrict__ Qh, const __nv_bfloat16* __restrict__ Ql,
    const __nv_bfloat16* __restrict__ Kh, const __nv_bfloat16* __restrict__ Kl,
    const __nv_bfloat16* __restrict__ Vh, const __nv_bfloat16* __restrict__ Vl,
    float* __restrict__ O)
{
    extern __shared__ __nv_bfloat16 sh[];

    const int tid  = threadIdx.x;
    const int lane = tid & 31, w = tid >> 5;
    const int g    = lane >> 2, t = lane & 3;
    const int bh   = blockIdx.y;
    const int q0   = blockIdx.x << 7;

    const __nv_bfloat16* Kbh = Kh + (size_t)bh * S_ * HD_;
    const __nv_bfloat16* Kbl = Kl + (size_t)bh * S_ * HD_;
    const __nv_bfloat16* Vbh = Vh + (size_t)bh * S_ * HD_;
    const __nv_bfloat16* Vbl = Vl + (size_t)bh * S_ * HD_;

    const uint32_t shB = (uint32_t)__cvta_generic_to_shared(sh);

    uint32_t qhf[2][4][4], qlf[2][4][4];
#pragma unroll
    for (int hf = 0; hf < 2; ++hf) {
        const __nv_bfloat16* Qbase = Qh + ((size_t)bh * S_ + q0 + (w << 5) + hf * 16) * HD_;
        const __nv_bfloat16* Qbl   = Ql + ((size_t)bh * S_ + q0 + (w << 5) + hf * 16) * HD_;
#pragma unroll
        for (int kb = 0; kb < 4; ++kb) {
            const int c0 = kb * 16 + 2 * t;
            qhf[hf][kb][0] = *(const uint32_t*)(Qbase + (size_t)g       * HD_ + c0);
            qhf[hf][kb][1] = *(const uint32_t*)(Qbase + (size_t)(g + 8) * HD_ + c0);
            qhf[hf][kb][2] = *(const uint32_t*)(Qbase + (size_t)g       * HD_ + c0 + 8);
            qhf[hf][kb][3] = *(const uint32_t*)(Qbase + (size_t)(g + 8) * HD_ + c0 + 8);
            qlf[hf][kb][0] = *(const uint32_t*)(Qbl   + (size_t)g       * HD_ + c0);
            qlf[hf][kb][1] = *(const uint32_t*)(Qbl   + (size_t)(g + 8) * HD_ + c0);
            qlf[hf][kb][2] = *(const uint32_t*)(Qbl   + (size_t)g       * HD_ + c0 + 8);
            qlf[hf][kb][3] = *(const uint32_t*)(Qbl   + (size_t)(g + 8) * HD_ + c0 + 8);
        }
    }

    const uint32_t kx4 = ((((lane >> 4) << 3) + (lane & 7)) * TP
                          + ((lane >> 3) & 1) * 8) * 2;
    const uint32_t vx4 = (((((lane >> 3) & 1) << 3) + (lane & 7)) * TP
                          + ((lane >> 4) & 1) * 8) * 2;

    float lsum[2][2] = {{0.f, 0.f}, {0.f, 0.f}};
    float o_[2][8][4];
#pragma unroll
    for (int hf = 0; hf < 2; hf++)
#pragma unroll
        for (int nb = 0; nb < 8; nb++)
#pragma unroll
            for (int j = 0; j < 4; j++) o_[hf][nb][j] = 0.f;

    const float SCALE = 0.18033688011112042f;  // log2(e)/8

    {
        const uint32_t st0 = shB;
        cp_tile(st0,                Kbh, tid);
        cp_tile(st0 + TSZ * 2,      Kbl, tid);
        cp_tile(st0 + 2 * TSZ * 2,  Vbh, tid);
        cp_tile(st0 + 3 * TSZ * 2,  Vbl, tid);
        CP_COMMIT();
    }

    int buf = 0;
    for (int kt = 0; kt < S_; kt += 64) {
        if (kt + 64 < S_) {
            const uint32_t stn = shB + (buf ^ 1) * 4 * TSZ * 2;
            const size_t goff = (size_t)(kt + 64) * HD_;
            cp_tile(stn,               Kbh + goff, tid);
            cp_tile(stn + TSZ * 2,     Kbl + goff, tid);
            cp_tile(stn + 2 * TSZ * 2, Vbh + goff, tid);
            cp_tile(stn + 3 * TSZ * 2, Vbl + goff, tid);
            CP_COMMIT();
            CP_WAIT(1);
        } else {
            CP_WAIT(0);
        }
        __syncthreads();

        const uint32_t KhiB = shB + buf * 4 * TSZ * 2;
        const uint32_t KloB = KhiB + TSZ * 2;
        const uint32_t VhiB = KhiB + 2 * TSZ * 2;
        const uint32_t VloB = KhiB + 3 * TSZ * 2;

        float S[2][8][4];
#pragma unroll
        for (int hf = 0; hf < 2; hf++)
#pragma unroll
            for (int nb = 0; nb < 8; nb++)
#pragma unroll
                for (int j = 0; j < 4; j++) S[hf][nb][j] = 0.f;

#pragma unroll
        for (int nb = 0; nb < 8; nb += 2) {
#pragma unroll
            for (int kb = 0; kb < 4; ++kb) {
                const uint32_t off = kx4 + (nb * 8 * TP + kb * 16) * 2;
                uint32_t h0, h1, h2, h3, e0, e1, e2, e3;
                LDSM_X4(h0, h1, h2, h3, KhiB + off);
                LDSM_X4(e0, e1, e2, e3, KloB + off);
#pragma unroll
                for (int hf = 0; hf < 2; ++hf) {
                    MMA_BF16(S[hf][nb],   qhf[hf][kb][0], qhf[hf][kb][1], qhf[hf][kb][2], qhf[hf][kb][3], h0, h1);
                    MMA_BF16(S[hf][nb],   qhf[hf][kb][0], qhf[hf][kb][1], qhf[hf][kb][2], qhf[hf][kb][3], e0, e1);
                    MMA_BF16(S[hf][nb],   qlf[hf][kb][0], qlf[hf][kb][1], qlf[hf][kb][2], qlf[hf][kb][3], h0, h1);
                    MMA_BF16(S[hf][nb+1], qhf[hf][kb][0], qhf[hf][kb][1], qhf[hf][kb][2], qhf[hf][kb][3], h2, h3);
                    MMA_BF16(S[hf][nb+1], qhf[hf][kb][0], qhf[hf][kb][1], qhf[hf][kb][2], qhf[hf][kb][3], e2, e3);
                    MMA_BF16(S[hf][nb+1], qlf[hf][kb][0], qlf[hf][kb][1], qlf[hf][kb][2], qlf[hf][kb][3], h2, h3);
                }
            }
        }

#pragma unroll
        for (int hf = 0; hf < 2; ++hf)
#pragma unroll
            for (int nb = 0; nb < 8; ++nb) {
                S[hf][nb][0] = ex2f(S[hf][nb][0] * SCALE);
                S[hf][nb][1] = ex2f(S[hf][nb][1] * SCALE);
                S[hf][nb][2] = ex2f(S[hf][nb][2] * SCALE);
                S[hf][nb][3] = ex2f(S[hf][nb][3] * SCALE);
                lsum[hf][0] += S[hf][nb][0] + S[hf][nb][1];
                lsum[hf][1] += S[hf][nb][2] + S[hf][nb][3];
            }

#pragma unroll
        for (int kb = 0; kb < 4; ++kb) {
            uint32_t phi[2][4], plo[2][4];
#pragma unroll
            for (int hf = 0; hf < 2; ++hf)
#pragma unroll
                for (int half = 0; half < 2; ++half) {
                    const float c0 = S[hf][2 * kb + half][0], c1 = S[hf][2 * kb + half][1];
                    const float c2 = S[hf][2 * kb + half][2], c3 = S[hf][2 * kb + half][3];
                    __nv_bfloat162 h0 = __floats2bfloat162_rn(c0, c1);
                    __nv_bfloat162 h1 = __floats2bfloat162_rn(c2, c3);
                    __nv_bfloat162 e0 = __floats2bfloat162_rn(c0 - __bfloat162float(h0.x),
                                                              c1 - __bfloat162float(h0.y));
                    __nv_bfloat162 e1 = __floats2bfloat162_rn(c2 - __bfloat162float(h1.x),
                                                              c3 - __bfloat162float(h1.y));
                    phi[hf][2 * half]     = *(uint32_t*)&h0;
                    phi[hf][2 * half + 1] = *(uint32_t*)&h1;
                    plo[hf][2 * half]     = *(uint32_t*)&e0;
                    plo[hf][2 * half + 1] = *(uint32_t*)&e1;
                }
#pragma unroll
            for (int nb = 0; nb < 8; nb += 2) {
                const uint32_t off = vx4 + (kb * 16 * TP + nb * 8) * 2;
                uint32_t vh0, vh1, vh2, vh3, vl0, vl1, vl2, vl3;
                LDSM_X4T(vh0, vh1, vh2, vh3, VhiB + off);
                LDSM_X4T(vl0, vl1, vl2, vl3, VloB + off);
#pragma unroll
                for (int hf = 0; hf < 2; ++hf) {
                    MMA_BF16(o_[hf][nb],   phi[hf][0], phi[hf][1], phi[hf][2], phi[hf][3], vh0, vh1);
                    MMA_BF16(o_[hf][nb],   phi[hf][0], phi[hf][1], phi[hf][2], phi[hf][3], vl0, vl1);
                    MMA_BF16(o_[hf][nb],   plo[hf][0], plo[hf][1], plo[hf][2], plo[hf][3], vh0, vh1);
                    MMA_BF16(o_[hf][nb+1], phi[hf][0], phi[hf][1], phi[hf][2], phi[hf][3], vh2, vh3);
                    MMA_BF16(o_[hf][nb+1], phi[hf][0], phi[hf][1], phi[hf][2], phi[hf][3], vl2, vl3);
                    MMA_BF16(o_[hf][nb+1], plo[hf][0], plo[hf][1], plo[hf][2], plo[hf][3], vh2, vh3);
                }
            }
        }
        __syncthreads();
        buf ^= 1;
    }

    // ---- epilogue: reduce l, O /= l, tf32-round, k-pair-permuted store ----
    const int b = bh >> 4, h = bh & 15;
    const int p0 = ((t & 1) << 2) + (t >> 1);
#pragma unroll
    for (int hf = 0; hf < 2; ++hf) {
        float l0 = lsum[hf][0], l1 = lsum[hf][1];
        l0 += __shfl_xor_sync(0xffffffffu, l0, 1);
        l0 += __shfl_xor_sync(0xffffffffu, l0, 2);
        l1 += __shfl_xor_sync(0xffffffffu, l1, 1);
        l1 += __shfl_xor_sync(0xffffffffu, l1, 2);
        const float inv0 = 1.f / l0, inv1 = 1.f / l1;
        const int row0 = q0 + (w << 5) + hf * 16 + g;
#pragma unroll
        for (int nb = 0; nb < 8; ++nb) {
            const int colb = h * HD_ + nb * 8;
            float* Or0 = O + (size_t)(b * S_ + row0) * D_ + colb;
            float* Or1 = O + (size_t)(b * S_ + row0 + 8) * D_ + colb;
            Or0[p0]     = rnd_tf32(o_[hf][nb][0] * inv0);
            Or0[p0 + 2] = rnd_tf32(o_[hf][nb][1] * inv0);
            Or1[p0]     = rnd_tf32(o_[hf][nb][2] * inv1);
            Or1[p0 + 2] = rnd_tf32(o_[hf][nb][3] * inv1);
        }
    }
}

// ---------------- launch ----------------
extern "C" void kernel_launch(void* const* d_in, const int* in_sizes, int n_in,
                              void* d_out, int out_size)
{
    const float* x        = (const float*)d_in[0];
    const float* w_qkv    = (const float*)d_in[1];
    const float* b_qkv    = (const float*)d_in[2];
    const float* w_out    = (const float*)d_in[3];
    const float* b_out    = (const float*)d_in[4];
    const float* ln_scale = (const float*)d_in[5];
    const float* ln_bias  = (const float*)d_in[6];
    const float* q_scale  = (const float*)d_in[7];
    const float* k_scale  = (const float*)d_in[8];
    float* out = (float*)d_out;

    float *xn, *qkv, *attn, *wqt, *wot;
    float2* rtab;
    __nv_bfloat16 *qh, *ql, *kh, *kl, *vh, *vl;
    cudaGetSymbolAddress((void**)&xn,   g_xn);
    cudaGetSymbolAddress((void**)&qkv,  g_qkv);
    cudaGetSymbolAddress((void**)&attn, g_attn);
    cudaGetSymbolAddress((void**)&wqt,  g_wqt);
    cudaGetSymbolAddress((void**)&wot,  g_wot);
    cudaGetSymbolAddress((void**)&rtab, g_rtab);
    cudaGetSymbolAddress((void**)&qh,   g_qh);
    cudaGetSymbolAddress((void**)&ql,   g_ql);
    cudaGetSymbolAddress((void**)&kh,   g_kh);
    cudaGetSymbolAddress((void**)&kl,   g_kl);
    cudaGetSymbolAddress((void**)&vh,   g_vh);
    cudaGetSymbolAddress((void**)&vl,   g_vl);

    const int attn_smem = 2 * 4 * TSZ * sizeof(__nv_bfloat16);            // 73728 B
    const int gemm_smem = 2 * (128 * 40 + 32 * 132) * sizeof(uint32_t);   // 74752 B
    cudaFuncSetAttribute(attn_kernel, cudaFuncAttributeMaxDynamicSharedMemorySize, attn_smem);
    cudaFuncSetAttribute(tf32_gemm_bias, cudaFuncAttributeMaxDynamicSharedMemorySize, gemm_smem);

    // QKV gemm is the 4th launch -> ncu profiles it.
    cvt_tf32_kernel<<<(D_ * 3 * D_) / 1024, 256>>>(w_qkv, wqt);
    ln_kernel<<<ROWS_, 256>>>(x, ln_scale, ln_bias, xn);
    rope_tab_kernel<<<(S_ * 32) / 256, 256>>>(rtab);
    tf32_gemm_bias<<<dim3((3 * D_) / 128, ROWS_ / 128), 256, gemm_smem>>>(
        xn, wqt, b_qkv, qkv, ROWS_, 3 * D_, D_);
    cvt_tf32_kernel<<<(D_ * D_) / 1024, 256>>>(w_out, wot);
    qk_rope_kernel<<<ROWS_, 512>>>(qkv, rtab, q_scale, k_scale, qh, ql, kh, kl, vh, vl);
    attn_kernel<<<dim3(S_ / 128, B_ * H_), 128, attn_smem>>>(qh, ql, kh, kl, vh, vl, attn);
    tf32_gemm_bias<<<dim3(D_ / 128, ROWS_ / 128), 256, gemm_smem>>>(
        attn, wot, b_out, out, ROWS_, D_, D_);
}

// round 16
// speedup vs baseline: 1.3254x; 1.2933x over previous
#include <cuda_runtime.h>
#include <cuda_fp16.h>
#include <stdint.h>
#include <math.h>

#define B_  2
#define S_  2048
#define D_  1024
#define H_  16
#define HD_ 64
#define ROWS_ (B_*S_)   // 4096

// ---------------- scratch (device globals; no allocations) ----------------
__device__ float g_xn  [ROWS_*D_];    // k-permuted within 8-blocks
__device__ float g_qkv [ROWS_*3*D_];
__device__ float g_attn[ROWS_*D_];    // k-permuted within 8-blocks
__device__ float g_wqt [D_*3*D_];     // tf32-rounded w_qkv
__device__ float g_wot [D_*D_];       // tf32-rounded w_out
__device__ float2 g_rtab[S_*32];      // RoPE cos/sin table
__device__ __half g_qf[B_*H_*S_*HD_];
__device__ __half g_kf[B_*H_*S_*HD_];
__device__ __half g_vh[B_*H_*S_*HD_];
__device__ __half g_vl[B_*H_*S_*HD_];

// ---------------- helpers ----------------
__device__ __forceinline__ uint32_t f2tf32(float x) {
    uint32_t r;
    asm("cvt.rna.tf32.f32 %0, %1;" : "=r"(r) : "f"(x));
    return r;
}
__device__ __forceinline__ float rnd_tf32(float x) {
    return __uint_as_float(f2tf32(x));
}

#define MMA_TF32(d, a, b)                                              \
    asm volatile("mma.sync.aligned.m16n8k8.row.col.f32.tf32.tf32.f32 " \
        "{%0,%1,%2,%3}, {%4,%5,%6,%7}, {%8,%9}, {%0,%1,%2,%3};"        \
        : "+f"((d)[0]), "+f"((d)[1]), "+f"((d)[2]), "+f"((d)[3])       \
        : "r"((a)[0]), "r"((a)[1]), "r"((a)[2]), "r"((a)[3]),          \
          "r"((b)[0]), "r"((b)[1]))

#define CP16(dst, src)                                                     \
    asm volatile("cp.async.ca.shared.global [%0], [%1], 16;"               \
        :: "r"(dst), "l"(src))
#define CP16CG(dst, src)                                                   \
    asm volatile("cp.async.cg.shared.global [%0], [%1], 16;"               \
        :: "r"(dst), "l"(src))
#define CP_COMMIT()  asm volatile("cp.async.commit_group;")
#define CP_WAIT(n)   asm volatile("cp.async.wait_group %0;" :: "n"(n))

// ---------------- kernel 0a: tf32-round a float array ----------------
__global__ __launch_bounds__(256) void cvt_tf32_kernel(
    const float* __restrict__ in, float* __restrict__ out)
{
    const int i = blockIdx.x * 256 + threadIdx.x;
    float4 v = ((const float4*)in)[i];
    v.x = rnd_tf32(v.x); v.y = rnd_tf32(v.y);
    v.z = rnd_tf32(v.z); v.w = rnd_tf32(v.w);
    ((float4*)out)[i] = v;
}

// ---------------- kernel 0b: RoPE table (fp64 once per (s,freq)) ----------
__global__ __launch_bounds__(256) void rope_tab_kernel(float2* __restrict__ tab)
{
    const int i = blockIdx.x * 256 + threadIdx.x;   // 0..65535
    const int s = i >> 5, f = i & 31;
    double invf = exp(-0.28782313662425575 * (double)f); // ln(10000)/32
    double sn, cs;
    sincos((double)s * invf, &sn, &cs);
    tab[i] = make_float2((float)cs, (float)sn);
}

// ---------------- kernel 1: LayerNorm -> tf32, k-pair-permuted ----------------
__global__ __launch_bounds__(256) void ln_kernel(
    const float* __restrict__ x, const float* __restrict__ g,
    const float* __restrict__ b, float* __restrict__ y)
{
    __shared__ float red[16];
    const int row = blockIdx.x, tid = threadIdx.x;
    const float* xr = x + (size_t)row * D_;
    float4 v = *(const float4*)(xr + (tid << 2));
    float s  = v.x + v.y + v.z + v.w;
    float ss = v.x*v.x + v.y*v.y + v.z*v.z + v.w*v.w;
#pragma unroll
    for (int off = 16; off; off >>= 1) {
        s  += __shfl_xor_sync(0xffffffffu, s,  off);
        ss += __shfl_xor_sync(0xffffffffu, ss, off);
    }
    if ((tid & 31) == 0) { red[tid >> 5] = s; red[8 + (tid >> 5)] = ss; }
    __syncthreads();
    if (tid < 8) {
        float a = red[tid], c = red[8 + tid];
#pragma unroll
        for (int off = 4; off; off >>= 1) {
            a += __shfl_xor_sync(0xffu, a, off);
            c += __shfl_xor_sync(0xffu, c, off);
        }
        if (tid == 0) { red[0] = a; red[8] = c; }
    }
    __syncthreads();
    const float mean = red[0] * (1.f / 1024.f);
    const float var  = red[8] * (1.f / 1024.f) - mean * mean;
    const float r    = rsqrtf(var + 1e-6f);
    const int c = tid << 2;
    float4 gv = *(const float4*)(g + c);
    float4 bv = *(const float4*)(b + c);
    float o0 = rnd_tf32((v.x - mean) * r * gv.x + bv.x);
    float o1 = rnd_tf32((v.y - mean) * r * gv.y + bv.y);
    float o2 = rnd_tf32((v.z - mean) * r * gv.z + bv.z);
    float o3 = rnd_tf32((v.w - mean) * r * gv.w + bv.w);
    float* yb = y + (size_t)row * D_ + (c & ~7) + ((c & 4) ? 1 : 0);
    yb[0] = o0; yb[2] = o1; yb[4] = o2; yb[6] = o3;
}

// ---------------- kernel 2/5: tf32 GEMM + bias, k-step 32, 2-stage --------
__global__ __launch_bounds__(256) void tf32_gemm_bias(
    const float* __restrict__ A, const float* __restrict__ Bm,
    const float* __restrict__ bias, float* __restrict__ C,
    int M, int N, int K)
{
    constexpr int AP = 40, BP = 132;
    constexpr int ASZ = 128 * AP;
    constexpr int BSZ = 32 * BP;
    extern __shared__ uint32_t gsm[];
    uint32_t* As = gsm;
    uint32_t* Bs = gsm + 2 * ASZ;

    const int tid  = threadIdx.x;
    const int wid  = tid >> 5, lane = tid & 31;
    const int g    = lane >> 2, t = lane & 3;
    const int wm   = wid & 1;
    const int wn   = wid >> 1;
    const int m0   = blockIdx.y << 7, n0 = blockIdx.x << 7;

    const uint32_t smemB = (uint32_t)__cvta_generic_to_shared(gsm);

    float acc[4][4][4];
#pragma unroll
    for (int mi = 0; mi < 4; mi++)
#pragma unroll
        for (int ni = 0; ni < 4; ni++)
#pragma unroll
            for (int r = 0; r < 4; r++) acc[mi][ni][r] = 0.f;

    auto load_stage = [&](int st, int ks) {
        const float* Asrc = A  + (size_t)m0 * K + ks * 32;
        const float* Bsrc = Bm + (size_t)(ks * 32) * N + n0;
        const uint32_t aB = smemB + (st * ASZ) * 4;
        const uint32_t bB = smemB + (2 * ASZ + st * BSZ) * 4;
#pragma unroll
        for (int it = 0; it < 4; ++it) {
            const int c  = tid + (it << 8);
            const int ar = c >> 3,  ak = (c & 7) << 2;
            CP16CG(aB + (ar * AP + ak) * 4, Asrc + (size_t)ar * K + ak);
            const int br = c >> 5,  bc = (c & 31) << 2;
            CP16CG(bB + (br * BP + bc) * 4, Bsrc + (size_t)br * N + bc);
        }
    };

    load_stage(0, 0); CP_COMMIT();

    const int KS = K >> 5;
    int buf = 0;
    for (int ks = 0; ks < KS; ++ks) {
        if (ks + 1 < KS) {
            load_stage(buf ^ 1, ks + 1);
            CP_COMMIT();
            CP_WAIT(1);
        } else {
            CP_WAIT(0);
        }
        __syncthreads();

        const uint32_t* Ab = As + buf * ASZ;
        const uint32_t* Bb = Bs + buf * BSZ;

#pragma unroll
        for (int kk = 0; kk < 32; kk += 8) {
            uint32_t af[4][4], bfr[4][2];
#pragma unroll
            for (int mi = 0; mi < 4; mi++) {
                const int rb = wm * 64 + mi * 16;
                uint2 p0 = *(const uint2*)&Ab[(rb + g)     * AP + kk + 2 * t];
                uint2 p1 = *(const uint2*)&Ab[(rb + 8 + g) * AP + kk + 2 * t];
                af[mi][0] = p0.x; af[mi][1] = p1.x;
                af[mi][2] = p0.y; af[mi][3] = p1.y;
            }
#pragma unroll
            for (int ni = 0; ni < 4; ni++) {
                const int cb = wn * 32 + ni * 8 + g;
                bfr[ni][0] = Bb[(kk + t)     * BP + cb];
                bfr[ni][1] = Bb[(kk + t + 4) * BP + cb];
            }
#pragma unroll
            for (int mi = 0; mi < 4; mi++)
#pragma unroll
                for (int ni = 0; ni < 4; ni++)
                    MMA_TF32(acc[mi][ni], af[mi], bfr[ni]);
        }
        __syncthreads();
        buf ^= 1;
    }

#pragma unroll
    for (int mi = 0; mi < 4; mi++) {
        const int row0 = m0 + wm * 64 + mi * 16 + g;
#pragma unroll
        for (int ni = 0; ni < 4; ni++) {
            const int col = n0 + wn * 32 + ni * 8 + 2 * t;
            float2 bb = *(const float2*)(bias + col);
            float2 v0 = { acc[mi][ni][0] + bb.x, acc[mi][ni][1] + bb.y };
            float2 v1 = { acc[mi][ni][2] + bb.x, acc[mi][ni][3] + bb.y };
            *(float2*)(C + (size_t)row0 * N + col)       = v0;
            *(float2*)(C + (size_t)(row0 + 8) * N + col) = v1;
        }
    }
}

// ---------------- kernel 3: per-head LN + RoPE -> fp16 -------------------
__device__ __forceinline__ float warp_allreduce_sum(float v) {
#pragma unroll
    for (int off = 16; off; off >>= 1) v += __shfl_xor_sync(0xffffffffu, v, off);
    return v;
}

__global__ __launch_bounds__(512) void qk_rope_kernel(
    const float* __restrict__ qkv, const float2* __restrict__ tab,
    const float* __restrict__ qsc, const float* __restrict__ ksc,
    __half* __restrict__ Qf, __half* __restrict__ Kf,
    __half* __restrict__ Vh, __half* __restrict__ Vl)
{
    const int bs   = blockIdx.x;
    const int b    = bs >> 11;
    const int s    = bs & (S_ - 1);
    const int h    = threadIdx.x >> 5;
    const int lane = threadIdx.x & 31;
    const float* base = qkv + (size_t)bs * (3 * D_) + h * HD_;

    float q0 = base[lane],        q1 = base[lane + 32];
    float k0 = base[1024 + lane], k1 = base[1024 + lane + 32];
    float v0 = base[2048 + lane], v1 = base[2048 + lane + 32];

    float mu  = warp_allreduce_sum(q0 + q1) * (1.f / 64.f);
    float d0  = q0 - mu, d1 = q1 - mu;
    float var = warp_allreduce_sum(d0*d0 + d1*d1) * (1.f / 64.f);
    float r   = rsqrtf(var + 1e-6f);
    float qn0 = d0 * r * qsc[lane];
    float qn1 = d1 * r * qsc[lane + 32];

    mu  = warp_allreduce_sum(k0 + k1) * (1.f / 64.f);
    d0  = k0 - mu; d1 = k1 - mu;
    var = warp_allreduce_sum(d0*d0 + d1*d1) * (1.f / 64.f);
    r   = rsqrtf(var + 1e-6f);
    float kn0 = d0 * r * ksc[lane];
    float kn1 = d1 * r * ksc[lane + 32];

    const float2 cs = tab[(s << 5) + lane];
    const float c = cs.x, si = cs.y;

    float qr0 = qn0 * c - qn1 * si;
    float qr1 = qn1 * c + qn0 * si;
    float kr0 = kn0 * c - kn1 * si;
    float kr1 = kn1 * c + kn0 * si;

    const size_t o = (((size_t)(b * H_ + h)) * S_ + s) * HD_ + lane;
    Qf[o]      = __float2half_rn(qr0);
    Qf[o + 32] = __float2half_rn(qr1);
    Kf[o]      = __float2half_rn(kr0);
    Kf[o + 32] = __float2half_rn(kr1);
    __half vh0 = __float2half_rn(v0);
    __half vh1 = __float2half_rn(v1);
    Vh[o]      = vh0;
    Vh[o + 32] = vh1;
    Vl[o]      = __float2half_rn(v0 - __half2float(vh0));
    Vl[o + 32] = __float2half_rn(v1 - __half2float(vh1));
}

// ---------------- fp16 mma helpers for attention ----------------
#define LDSM_X4(r0,r1,r2,r3,addr)                                          \
    asm volatile("ldmatrix.sync.aligned.m8n8.x4.shared.b16 {%0,%1,%2,%3}, [%4];" \
        : "=r"(r0), "=r"(r1), "=r"(r2), "=r"(r3) : "r"(addr))

#define LDSM_X4T(r0,r1,r2,r3,addr)                                         \
    asm volatile("ldmatrix.sync.aligned.m8n8.x4.trans.shared.b16 {%0,%1,%2,%3}, [%4];" \
        : "=r"(r0), "=r"(r1), "=r"(r2), "=r"(r3) : "r"(addr))

#define MMA_F16(d, a0,a1,a2,a3, b0,b1)                                     \
    asm volatile("mma.sync.aligned.m16n8k16.row.col.f32.f16.f16.f32 "      \
        "{%0,%1,%2,%3}, {%4,%5,%6,%7}, {%8,%9}, {%0,%1,%2,%3};"            \
        : "+f"((d)[0]), "+f"((d)[1]), "+f"((d)[2]), "+f"((d)[3])           \
        : "r"(a0), "r"(a1), "r"(a2), "r"(a3), "r"(b0), "r"(b1))

__device__ __forceinline__ float ex2f(float x) {
    float y; asm("ex2.approx.f32 %0, %1;" : "=f"(y) : "f"(x)); return y;
}

#define TP 72
#define TSZ (64 * TP)

__device__ __forceinline__ void cp_tile(
    uint32_t dst, const __half* __restrict__ src, int tid)
{
#pragma unroll
    for (int it = 0; it < 4; ++it) {
        int c = tid + (it << 7);
        int r = c >> 3, cc = c & 7;
        CP16(dst + r * (TP * 2) + cc * 16, src + r * HD_ + cc * 8);
    }
}

// ---------------- kernel 4: flash attention (fp16, 128-row Q tile) ---------
// Q,K,P in single fp16; V as fp16 hi/lo pair. No-max softmax (scores <= 8).
__global__ __launch_bounds__(128, 2) void attn_kernel(
    const __half* __restrict__ Qf, const __half* __restrict__ Kf,
    const __half* __restrict__ Vh, const __half* __restrict__ Vl,
    float* __restrict__ O)
{
    extern __shared__ __half sh[];   // [2 stages][3 tiles][TSZ]

    const int tid  = threadIdx.x;
    const int lane = tid & 31, w = tid >> 5;
    const int g    = lane >> 2, t = lane & 3;
    const int bh   = blockIdx.y;
    const int q0   = blockIdx.x << 7;

    const __half* Kb  = Kf + (size_t)bh * S_ * HD_;
    const __half* Vbh = Vh + (size_t)bh * S_ * HD_;
    const __half* Vbl = Vl + (size_t)bh * S_ * HD_;

    const uint32_t shB = (uint32_t)__cvta_generic_to_shared(sh);
    constexpr uint32_t STG = 3 * TSZ * 2;   // bytes per stage

    // ---- Q A-fragments straight from gmem (once); two 16-row halves ----
    uint32_t qf[2][4][4];
#pragma unroll
    for (int hf = 0; hf < 2; ++hf) {
        const __half* Qb = Qf + ((size_t)bh * S_ + q0 + (w << 5) + hf * 16) * HD_;
#pragma unroll
        for (int kb = 0; kb < 4; ++kb) {
            const int c0 = kb * 16 + 2 * t;
            qf[hf][kb][0] = *(const uint32_t*)(Qb + (size_t)g       * HD_ + c0);
            qf[hf][kb][1] = *(const uint32_t*)(Qb + (size_t)(g + 8) * HD_ + c0);
            qf[hf][kb][2] = *(const uint32_t*)(Qb + (size_t)g       * HD_ + c0 + 8);
            qf[hf][kb][3] = *(const uint32_t*)(Qb + (size_t)(g + 8) * HD_ + c0 + 8);
        }
    }

    const uint32_t kx4 = ((((lane >> 4) << 3) + (lane & 7)) * TP
                          + ((lane >> 3) & 1) * 8) * 2;
    const uint32_t vx4 = (((((lane >> 3) & 1) << 3) + (lane & 7)) * TP
                          + ((lane >> 4) & 1) * 8) * 2;

    float lsum[2][2] = {{0.f, 0.f}, {0.f, 0.f}};
    float o_[2][8][4];
#pragma unroll
    for (int hf = 0; hf < 2; hf++)
#pragma unroll
        for (int nb = 0; nb < 8; nb++)
#pragma unroll
            for (int j = 0; j < 4; j++) o_[hf][nb][j] = 0.f;

    const float SCALE = 0.18033688011112042f;  // log2(e)/8

    {
        const uint32_t st0 = shB;
        cp_tile(st0,               Kb,  tid);
        cp_tile(st0 + TSZ * 2,     Vbh, tid);
        cp_tile(st0 + 2 * TSZ * 2, Vbl, tid);
        CP_COMMIT();
    }

    int buf = 0;
    for (int kt = 0; kt < S_; kt += 64) {
        if (kt + 64 < S_) {
            const uint32_t stn = shB + (buf ^ 1) * STG;
            const size_t goff = (size_t)(kt + 64) * HD_;
            cp_tile(stn,               Kb  + goff, tid);
            cp_tile(stn + TSZ * 2,     Vbh + goff, tid);
            cp_tile(stn + 2 * TSZ * 2, Vbl + goff, tid);
            CP_COMMIT();
            CP_WAIT(1);
        } else {
            CP_WAIT(0);
        }
        __syncthreads();

        const uint32_t KfB  = shB + buf * STG;
        const uint32_t VhB  = KfB + TSZ * 2;
        const uint32_t VlB  = KfB + 2 * TSZ * 2;

        // ---- S = Q K^T (both halves share K ldmatrix) ----
        float S[2][8][4];
#pragma unroll
        for (int hf = 0; hf < 2; hf++)
#pragma unroll
            for (int nb = 0; nb < 8; nb++)
#pragma unroll
                for (int j = 0; j < 4; j++) S[hf][nb][j] = 0.f;

#pragma unroll
        for (int nb = 0; nb < 8; nb += 2) {
#pragma unroll
            for (int kb = 0; kb < 4; ++kb) {
                const uint32_t off = kx4 + (nb * 8 * TP + kb * 16) * 2;
                uint32_t k0, k1, k2, k3;
                LDSM_X4(k0, k1, k2, k3, KfB + off);
#pragma unroll
                for (int hf = 0; hf < 2; ++hf) {
                    MMA_F16(S[hf][nb],   qf[hf][kb][0], qf[hf][kb][1], qf[hf][kb][2], qf[hf][kb][3], k0, k1);
                    MMA_F16(S[hf][nb+1], qf[hf][kb][0], qf[hf][kb][1], qf[hf][kb][2], qf[hf][kb][3], k2, k3);
                }
            }
        }

        // ---- P = 2^(S*log2e/8); accumulate l (no-max, exact) ----
#pragma unroll
        for (int hf = 0; hf < 2; ++hf)
#pragma unroll
            for (int nb = 0; nb < 8; ++nb) {
                S[hf][nb][0] = ex2f(S[hf][nb][0] * SCALE);
                S[hf][nb][1] = ex2f(S[hf][nb][1] * SCALE);
                S[hf][nb][2] = ex2f(S[hf][nb][2] * SCALE);
                S[hf][nb][3] = ex2f(S[hf][nb][3] * SCALE);
                lsum[hf][0] += S[hf][nb][0] + S[hf][nb][1];
                lsum[hf][1] += S[hf][nb][2] + S[hf][nb][3];
            }

        // ---- O += P (Vh + Vl); V ldmatrix shared across halves ----
#pragma unroll
        for (int kb = 0; kb < 4; ++kb) {
            uint32_t ph[2][4];
#pragma unroll
            for (int hf = 0; hf < 2; ++hf)
#pragma unroll
                for (int half = 0; half < 2; ++half) {
                    __half2 p01 = __floats2half2_rn(S[hf][2*kb+half][0], S[hf][2*kb+half][1]);
                    __half2 p23 = __floats2half2_rn(S[hf][2*kb+half][2], S[hf][2*kb+half][3]);
                    ph[hf][2 * half]     = *(uint32_t*)&p01;
                    ph[hf][2 * half + 1] = *(uint32_t*)&p23;
                }
#pragma unroll
            for (int nb = 0; nb < 8; nb += 2) {
                const uint32_t off = vx4 + (kb * 16 * TP + nb * 8) * 2;
                uint32_t vh0, vh1, vh2, vh3, vl0, vl1, vl2, vl3;
                LDSM_X4T(vh0, vh1, vh2, vh3, VhB + off);
                LDSM_X4T(vl0, vl1, vl2, vl3, VlB + off);
#pragma unroll
                for (int hf = 0; hf < 2; ++hf) {
                    MMA_F16(o_[hf][nb],   ph[hf][0], ph[hf][1], ph[hf][2], ph[hf][3], vh0, vh1);
                    MMA_F16(o_[hf][nb],   ph[hf][0], ph[hf][1], ph[hf][2], ph[hf][3], vl0, vl1);
                    MMA_F16(o_[hf][nb+1], ph[hf][0], ph[hf][1], ph[hf][2], ph[hf][3], vh2, vh3);
                    MMA_F16(o_[hf][nb+1], ph[hf][0], ph[hf][1], ph[hf][2], ph[hf][3], vl2, vl3);
                }
            }
        }
        __syncthreads();
        buf ^= 1;
    }

    // ---- epilogue: reduce l, O /= l, tf32-round, k-pair-permuted store ----
    const int b = bh >> 4, h = bh & 15;
    const int p0 = ((t & 1) << 2) + (t >> 1);
#pragma unroll
    for (int hf = 0; hf < 2; ++hf) {
        float l0 = lsum[hf][0], l1 = lsum[hf][1];
        l0 += __shfl_xor_sync(0xffffffffu, l0, 1);
        l0 += __shfl_xor_sync(0xffffffffu, l0, 2);
        l1 += __shfl_xor_sync(0xffffffffu, l1, 1);
        l1 += __shfl_xor_sync(0xffffffffu, l1, 2);
        const float inv0 = 1.f / l0, inv1 = 1.f / l1;
        const int row0 = q0 + (w << 5) + hf * 16 + g;
#pragma unroll
        for (int nb = 0; nb < 8; ++nb) {
            const int colb = h * HD_ + nb * 8;
            float* Or0 = O + (size_t)(b * S_ + row0) * D_ + colb;
            float* Or1 = O + (size_t)(b * S_ + row0 + 8) * D_ + colb;
            Or0[p0]     = rnd_tf32(o_[hf][nb][0] * inv0);
            Or0[p0 + 2] = rnd_tf32(o_[hf][nb][1] * inv0);
            Or1[p0]     = rnd_tf32(o_[hf][nb][2] * inv1);
            Or1[p0 + 2] = rnd_tf32(o_[hf][nb][3] * inv1);
        }
    }
}

// ---------------- launch ----------------
extern "C" void kernel_launch(void* const* d_in, const int* in_sizes, int n_in,
                              void* d_out, int out_size)
{
    const float* x        = (const float*)d_in[0];
    const float* w_qkv    = (const float*)d_in[1];
    const float* b_qkv    = (const float*)d_in[2];
    const float* w_out    = (const float*)d_in[3];
    const float* b_out    = (const float*)d_in[4];
    const float* ln_scale = (const float*)d_in[5];
    const float* ln_bias  = (const float*)d_in[6];
    const float* q_scale  = (const float*)d_in[7];
    const float* k_scale  = (const float*)d_in[8];
    float* out = (float*)d_out;

    float *xn, *qkv, *attn, *wqt, *wot;
    float2* rtab;
    __half *qf, *kf, *vh, *vl;
    cudaGetSymbolAddress((void**)&xn,   g_xn);
    cudaGetSymbolAddress((void**)&qkv,  g_qkv);
    cudaGetSymbolAddress((void**)&attn, g_attn);
    cudaGetSymbolAddress((void**)&wqt,  g_wqt);
    cudaGetSymbolAddress((void**)&wot,  g_wot);
    cudaGetSymbolAddress((void**)&rtab, g_rtab);
    cudaGetSymbolAddress((void**)&qf,   g_qf);
    cudaGetSymbolAddress((void**)&kf,   g_kf);
    cudaGetSymbolAddress((void**)&vh,   g_vh);
    cudaGetSymbolAddress((void**)&vl,   g_vl);

    const int attn_smem = 2 * 3 * TSZ * sizeof(__half);                   // 55296 B
    const int gemm_smem = 2 * (128 * 40 + 32 * 132) * sizeof(uint32_t);   // 74752 B
    cudaFuncSetAttribute(attn_kernel, cudaFuncAttributeMaxDynamicSharedMemorySize, attn_smem);
    cudaFuncSetAttribute(tf32_gemm_bias, cudaFuncAttributeMaxDynamicSharedMemorySize, gemm_smem);

    // QKV gemm is the 4th launch -> ncu profiles it.
    cvt_tf32_kernel<<<(D_ * 3 * D_) / 1024, 256>>>(w_qkv, wqt);
    ln_kernel<<<ROWS_, 256>>>(x, ln_scale, ln_bias, xn);
    rope_tab_kernel<<<(S_ * 32) / 256, 256>>>(rtab);
    tf32_gemm_bias<<<dim3((3 * D_) / 128, ROWS_ / 128), 256, gemm_smem>>>(
        xn, wqt, b_qkv, qkv, ROWS_, 3 * D_, D_);
    cvt_tf32_kernel<<<(D_ * D_) / 1024, 256>>>(w_out, wot);
    qk_rope_kernel<<<ROWS_, 512>>>(qkv, rtab, q_scale, k_scale, qf, kf, vh, vl);
    attn_kernel<<<dim3(S_ / 128, B_ * H_), 128, attn_smem>>>(qf, kf, vh, vl, attn);
    tf32_gemm_bias<<<dim3(D_ / 128, ROWS_ / 128), 256, gemm_smem>>>(
        attn, wot, b_out, out, ROWS_, D_, D_);
}